// round 8
// baseline (speedup 1.0000x reference)
#include <cuda_runtime.h>
#include <cstdint>

#define HH 128
#define WHX 128
#define H 256
#define W 256
#define NB 4
#define CF 64
#define KK 51
#define PADK 25
#define HP (H + 2*PADK)   // 306
#define WPP (W + 2*PADK)  // 306
#define HW (H*W)          // 65536

typedef unsigned long long ull;

__device__ __forceinline__ ull pack2(float lo, float hi) {
    ull r; asm("mov.b64 %0, {%1, %2};" : "=l"(r) : "f"(lo), "f"(hi)); return r;
}
__device__ __forceinline__ void unpack2(ull v, float& lo, float& hi) {
    asm("mov.b64 {%0, %1}, %2;" : "=f"(lo), "=f"(hi) : "l"(v));
}
__device__ __forceinline__ ull ffma2(ull a, ull b, ull c) {
    ull d; asm("fma.rn.f32x2 %0, %1, %2, %3;" : "=l"(d) : "l"(a), "l"(b), "l"(c)); return d;
}
__device__ __forceinline__ uint32_t smem_u32(const void* p) {
    return (uint32_t)__cvta_generic_to_shared(p);
}
__device__ __forceinline__ void cpa16(uint32_t dst, const void* src, int srcsize) {
    asm volatile("cp.async.cg.shared.global [%0], [%1], 16, %2;\n"
                 :: "r"(dst), "l"(src), "r"(srcsize));
}
__device__ __forceinline__ void cpa8(uint32_t dst, const void* src) {
    asm volatile("cp.async.ca.shared.global [%0], [%1], 8;\n"
                 :: "r"(dst), "l"(src));
}
#define CP_COMMIT() asm volatile("cp.async.commit_group;\n" ::: "memory")
#define CP_WAIT0()  asm volatile("cp.async.wait_group 0;\n" ::: "memory")
#define CP_WAIT1()  asm volatile("cp.async.wait_group 1;\n" ::: "memory")

// Scratch buffers (allocation-free: static device globals)
__device__ float g_up[(size_t)NB*CF*H*W];
__device__ float g_t1[(size_t)4*NB*KK*H*W];
__device__ float g_t2[(size_t)4*NB*KK*H*W];
__device__ float g_k [(size_t)4*NB*KK*H*W];   // k=0:k1v 1:k1h 2:k2v 3:k2h
// packed weights: [k][grp(3)][ic][tap(9)][ocpair(9)] float2
__device__ float2 g_wp1[(size_t)4*3*CF*81];
__device__ float2 g_wp2[(size_t)4*3*KK*81];
__device__ float2 g_wp3[(size_t)4*3*KK*81];

// ---------------------------------------------------------------------------
__global__ void pack_weights(const float* __restrict__ wgt, float2* __restrict__ wp, int CIN)
{
    int idx = blockIdx.x * blockDim.x + threadIdx.x;
    int total = 4*3*CIN*81;
    if (idx >= total) return;
    int op  = idx % 9;
    int tap = (idx / 9) % 9;
    int ic  = (idx / 81) % CIN;
    int grp = (idx / (81*CIN)) % 3;
    int k   = idx / (81*CIN*3);
    int oc  = grp*18 + 2*op;
    float lo = (oc     < KK) ? wgt[((size_t)(k*KK + oc    )*CIN + ic)*9 + tap] : 0.f;
    float hi = (oc + 1 < KK) ? wgt[((size_t)(k*KK + oc + 1)*CIN + ic)*9 + tap] : 0.f;
    wp[idx] = make_float2(lo, hi);
}

// ---------------------------------------------------------------------------
// 2x bilinear upsample, align_corners=True
// ---------------------------------------------------------------------------
__global__ void upsample_kernel(const float* __restrict__ x, float* __restrict__ out)
{
    int idx = blockIdx.x * blockDim.x + threadIdx.x;
    if (idx >= NB*CF*H*W) return;
    int wo = idx & (W-1);
    int ho = (idx >> 8) & (H-1);
    int bc = idx >> 16;
    const float s = (float)(HH - 1) / (float)(H - 1);
    float py = ho * s;
    float px = wo * s;
    int y0 = (int)floorf(py); int y1 = min(y0 + 1, HH - 1);
    int x0 = (int)floorf(px); int x1 = min(x0 + 1, WHX - 1);
    float wy = py - (float)y0, wx = px - (float)x0;
    const float* p = x + (size_t)bc * HH * WHX;
    float a = p[y0*WHX + x0], b = p[y0*WHX + x1];
    float c = p[y1*WHX + x0], d = p[y1*WHX + x1];
    float top = a*(1.f-wx) + b*wx;
    float bot = c*(1.f-wx) + d*wx;
    out[idx] = top*(1.f-wy) + bot*wy;
}

// ---------------------------------------------------------------------------
// Direct 3x3 conv + bias + relu. Warp = one output row (conflict-free LDS).
// Block 256 thr: tx = tid&31 (32 px-pairs, 64 px wide), ty = tid>>5 (8 rows).
// Each thread: 2 horizontal px x 9 oc-pairs packed f32x2 = 18 packed accs.
// Input tile 10 rows x 72 cols, 3-stage cp.async pipeline (buffers rotate
// strictly as ic % 3). Weights pre-packed [ic][tap][ocpair] float2 in gmem.
// grid: (W/64, H/8, 4*NB*3)
// ---------------------------------------------------------------------------
template<int CIN, bool IN_PER_K>
__global__ void __launch_bounds__(256, 2)
conv3x3_relu4(const float* __restrict__ in, const float2* __restrict__ wpack,
              const float* __restrict__ bias, float* __restrict__ out)
{
    const int NGRP = 3;
    const int SROW = 72;
    const int TROWS = 10;
    const int TILE = TROWS*SROW;            // 720 floats
    const int NCHUNK = TROWS*18;            // 180 x 16B chunks
    const int WOFF = (CIN*162 + 3) & ~3;    // float offset of s_in (16B aligned)

    int z   = blockIdx.z;
    int k   = z / (NB*NGRP);
    int r2  = z % (NB*NGRP);
    int b   = r2 / NGRP;
    int ocg = r2 % NGRP;
    int oc0 = ocg * 18;
    int gx0 = blockIdx.x * 64;
    int gy0 = blockIdx.y * 8;

    extern __shared__ float sm[];
    float2* s_w2 = (float2*)sm;        // [CIN][9][9]
    float*  s_in = sm + WOFF;          // [3][10][72]

    int tid = threadIdx.x;
    int tx = tid & 31, ty = tid >> 5;

    // stage packed weights (linear, async; joins first commit group)
    {
        const float2* wsrc = wpack + (size_t)(k*NGRP + ocg) * CIN * 81;
        uint32_t wdst = smem_u32(s_w2);
        for (int i = tid; i < CIN*81; i += 256)
            cpa8(wdst + i*8, wsrc + i);
    }

    const float* ip = in + (size_t)(IN_PER_K ? (k*NB + b) : b) * CIN * HW;
    uint32_t sin_base = smem_u32(s_in);

    auto stage = [&](int ic) {
        const float* cp = ip + (size_t)ic * HW;
        uint32_t dst = sin_base + (ic % 3)*TILE*4;
        for (int i = tid; i < NCHUNK; i += 256) {
            int rr = i / 18, f = i % 18;
            int gy = gy0 - 1 + rr;
            int gx = gx0 - 4 + 4*f;
            bool ok = ((unsigned)gy < H) && (gx >= 0) && (gx < W);
            cpa16(dst + (rr*SROW + f*4)*4, ok ? (cp + gy*W + gx) : cp, ok ? 16 : 0);
        }
        CP_COMMIT();
    };

    stage(0);
    stage(1);

    ull acc[9][2];
    #pragma unroll
    for (int o = 0; o < 9; o++) { acc[o][0] = 0ULL; acc[o][1] = 0ULL; }

    #pragma unroll 1
    for (int ic = 0; ic < CIN; ic++) {
        if (ic == CIN - 1) { CP_WAIT0(); } else { CP_WAIT1(); }
        __syncthreads();
        if (ic + 2 < CIN) stage(ic + 2);

        const float* sb = s_in + (ic % 3)*TILE;
        const ull* wq = (const ull*)s_w2 + (size_t)ic*81;

        #pragma unroll
        for (int r = 0; r < 3; r++) {
            const float2* vp = (const float2*)(sb + (ty + r)*SROW + 2*tx + 2);
            float2 va = vp[0], vb = vp[1], vc = vp[2];
            ull P1 = pack2(va.y, va.y);
            ull P2 = pack2(vb.x, vb.x);
            ull P3 = pack2(vb.y, vb.y);
            ull P4 = pack2(vc.x, vc.x);
            #pragma unroll
            for (int op = 0; op < 9; op++) {
                ull w0 = wq[(r*3 + 0)*9 + op];
                ull w1 = wq[(r*3 + 1)*9 + op];
                ull w2 = wq[(r*3 + 2)*9 + op];
                acc[op][0] = ffma2(w0, P1, acc[op][0]);
                acc[op][0] = ffma2(w1, P2, acc[op][0]);
                acc[op][0] = ffma2(w2, P3, acc[op][0]);
                acc[op][1] = ffma2(w0, P2, acc[op][1]);
                acc[op][1] = ffma2(w1, P3, acc[op][1]);
                acc[op][1] = ffma2(w2, P4, acc[op][1]);
            }
        }
    }

    // epilogue: bias + relu + store (2 px per oc as float2)
    float* outp = out + (size_t)(k*NB + b) * KK * HW;
    int oy = gy0 + ty, ox = gx0 + 2*tx;
    #pragma unroll
    for (int opi = 0; opi < 9; opi++) {
        float l0, h0, l1, h1;
        unpack2(acc[opi][0], l0, h0);
        unpack2(acc[opi][1], l1, h1);
        int oc = oc0 + 2*opi;
        if (oc < KK) {
            float bv = bias[k*KK + oc];
            float2 v = make_float2(fmaxf(l0 + bv, 0.f), fmaxf(l1 + bv, 0.f));
            *(float2*)(outp + (size_t)oc*HW + oy*W + ox) = v;
        }
        if (oc + 1 < KK) {
            float bv = bias[k*KK + oc + 1];
            float2 v = make_float2(fmaxf(h0 + bv, 0.f), fmaxf(h1 + bv, 0.f));
            *(float2*)(outp + (size_t)(oc+1)*HW + oy*W + ox) = v;
        }
    }
}

// ---------------------------------------------------------------------------
// Adaptive separable conv, 2 vertically adjacent outputs per thread sharing
// the row-window LDS. Packed f32x2 over taps with parity phase.
// grid: (W/32, H/16, NB), block (32, 8). Tile 32x16 outputs, 66-row smem.
// ---------------------------------------------------------------------------
__global__ void __launch_bounds__(256)
sepconv3_kernel(const float* __restrict__ i1, const float* __restrict__ i2,
                const float* __restrict__ gk, float* __restrict__ out)
{
    const int SW = 84;
    int b   = blockIdx.z;
    int gx0 = blockIdx.x * 32;
    int gy0 = blockIdx.y * 16;
    int tx  = threadIdx.x, ty = threadIdx.y;
    int tid = ty * 32 + tx;
    int x  = gx0 + tx;
    int y0 = gy0 + 2*ty;
    int q = tx & 1;
    int col0 = tx - q;

    __shared__ __align__(16) float s_img[66 * SW];

    float accA[3] = {0.f, 0.f, 0.f};
    float accB[3] = {0.f, 0.f, 0.f};

    #pragma unroll 1
    for (int im = 0; im < 2; im++) {
        const float* ip   = im ? i2 : i1;
        const float* kvp0 = gk + (((size_t)(im*2 + 0)*NB + b)*KK)*HW + (size_t)y0*W + x;
        const float* kvp1 = kvp0 + W;
        const float* khp0 = gk + (((size_t)(im*2 + 1)*NB + b)*KK)*HW + (size_t)y0*W + x;
        const float* khp1 = khp0 + W;

        ull KP0[26], KP1[26];
        #pragma unroll
        for (int m = 0; m < 26; m++) {
            int t0 = 2*m - q, t1 = 2*m + 1 - q;
            float a0 = ((unsigned)t0 < KK) ? khp0[(size_t)t0 * HW] : 0.f;
            float a1 = ((unsigned)t1 < KK) ? khp0[(size_t)t1 * HW] : 0.f;
            KP0[m] = pack2(a0, a1);
            float b0 = ((unsigned)t0 < KK) ? khp1[(size_t)t0 * HW] : 0.f;
            float b1 = ((unsigned)t1 < KK) ? khp1[(size_t)t1 * HW] : 0.f;
            KP1[m] = pack2(b0, b1);
        }

        #pragma unroll 1
        for (int c = 0; c < 3; c++) {
            const float* cp = ip + ((size_t)b*3 + c) * HP * WPP;
            __syncthreads();
            for (int i = tid; i < 66*SW; i += 256) {
                int rr = i / SW, cc = i % SW;
                s_img[i] = (cc < 82) ? cp[(size_t)(gy0 + rr)*WPP + gx0 + cc] : 0.f;
            }
            __syncthreads();

            ull A0 = 0ULL, A1 = 0ULL;
            #pragma unroll 1
            for (int t = 0; t < 52; t++) {
                const ull* rp = (const ull*)(s_img + (2*ty + t)*SW + col0);
                ull hs0 = 0ULL, hs1 = 0ULL;
                #pragma unroll
                for (int m = 0; m < 26; m++) {
                    ull v = rp[m];
                    hs0 = ffma2(KP0[m], v, hs0);
                    hs1 = ffma2(KP1[m], v, hs1);
                }
                if (t < 51) {
                    float kv = kvp0[(size_t)t * HW];
                    A0 = ffma2(pack2(kv, kv), hs0, A0);
                }
                if (t >= 1) {
                    float kv = kvp1[(size_t)(t-1) * HW];
                    A1 = ffma2(pack2(kv, kv), hs1, A1);
                }
            }
            float lo, hi;
            unpack2(A0, lo, hi); accA[c] += lo + hi;
            unpack2(A1, lo, hi); accB[c] += lo + hi;
        }
    }

    size_t ob0 = ((size_t)b*3)*HW + (size_t)y0*W + x;
    size_t ob1 = ob0 + W;
    out[ob0]        = accA[0];
    out[ob0 + HW]   = accA[1];
    out[ob0 + 2*HW] = accA[2];
    out[ob1]        = accB[0];
    out[ob1 + HW]   = accB[1];
    out[ob1 + 2*HW] = accB[2];
}

// ---------------------------------------------------------------------------
extern "C" void kernel_launch(void* const* d_in, const int* in_sizes, int n_in,
                              void* d_out, int out_size)
{
    const float* x  = (const float*)d_in[0];
    const float* i1 = (const float*)d_in[1];
    const float* i2 = (const float*)d_in[2];
    const float* W1 = (const float*)d_in[3];
    const float* B1 = (const float*)d_in[4];
    const float* W2 = (const float*)d_in[5];
    const float* B2 = (const float*)d_in[6];
    const float* W3 = (const float*)d_in[7];
    const float* B3 = (const float*)d_in[8];
    float* out = (float*)d_out;

    float* up = nullptr; float* t1 = nullptr; float* t2 = nullptr; float* kk = nullptr;
    float2* wp1 = nullptr; float2* wp2 = nullptr; float2* wp3 = nullptr;
    cudaGetSymbolAddress((void**)&up, g_up);
    cudaGetSymbolAddress((void**)&t1, g_t1);
    cudaGetSymbolAddress((void**)&t2, g_t2);
    cudaGetSymbolAddress((void**)&kk, g_k);
    cudaGetSymbolAddress((void**)&wp1, g_wp1);
    cudaGetSymbolAddress((void**)&wp2, g_wp2);
    cudaGetSymbolAddress((void**)&wp3, g_wp3);

    const int WOFF64 = (64*162 + 3) & ~3;
    const int WOFF51 = (51*162 + 3) & ~3;
    size_t smem64 = (size_t)(WOFF64 + 3*10*72) * sizeof(float);
    size_t smem51 = (size_t)(WOFF51 + 3*10*72) * sizeof(float);
    cudaFuncSetAttribute(conv3x3_relu4<64, false>,
                         cudaFuncAttributeMaxDynamicSharedMemorySize, (int)smem64);
    cudaFuncSetAttribute(conv3x3_relu4<51, true>,
                         cudaFuncAttributeMaxDynamicSharedMemorySize, (int)smem51);

    // 0) pack weights (tiny)
    {
        int t64 = 4*3*64*81, t51 = 4*3*51*81;
        pack_weights<<<(t64 + 255)/256, 256>>>(W1, wp1, 64);
        pack_weights<<<(t51 + 255)/256, 256>>>(W2, wp2, 51);
        pack_weights<<<(t51 + 255)/256, 256>>>(W3, wp3, 51);
    }

    // 1) upsample features
    {
        int n = NB*CF*H*W;
        upsample_kernel<<<(n + 255)/256, 256>>>(x, up);
    }

    // 2) three conv stages
    dim3 cgrid(W/64, H/8, 4*NB*3);
    conv3x3_relu4<64, false><<<cgrid, 256, smem64>>>(up, wp1, B1, t1);
    conv3x3_relu4<51, true ><<<cgrid, 256, smem51>>>(t1, wp2, B2, t2);
    conv3x3_relu4<51, true ><<<cgrid, 256, smem51>>>(t2, wp3, B3, kk);

    // 3) separable filtering of both images + sum
    {
        dim3 g(W/32, H/16, NB);
        dim3 blk(32, 8);
        sepconv3_kernel<<<g, blk>>>(i1, i2, kk, out);
    }
}

// round 9
// speedup vs baseline: 1.1853x; 1.1853x over previous
#include <cuda_runtime.h>
#include <cstdint>

#define HH 128
#define WHX 128
#define H 256
#define W 256
#define NB 4
#define CF 64
#define KK 51
#define PADK 25
#define HP (H + 2*PADK)   // 306
#define WPP (W + 2*PADK)  // 306
#define HW (H*W)          // 65536

typedef unsigned long long ull;

__device__ __forceinline__ ull pack2(float lo, float hi) {
    ull r; asm("mov.b64 %0, {%1, %2};" : "=l"(r) : "f"(lo), "f"(hi)); return r;
}
__device__ __forceinline__ void unpack2(ull v, float& lo, float& hi) {
    asm("mov.b64 {%0, %1}, %2;" : "=f"(lo), "=f"(hi) : "l"(v));
}
__device__ __forceinline__ ull ffma2(ull a, ull b, ull c) {
    ull d; asm("fma.rn.f32x2 %0, %1, %2, %3;" : "=l"(d) : "l"(a), "l"(b), "l"(c)); return d;
}
__device__ __forceinline__ uint32_t smem_u32(const void* p) {
    return (uint32_t)__cvta_generic_to_shared(p);
}
__device__ __forceinline__ void cpa16(uint32_t dst, const void* src, int srcsize) {
    asm volatile("cp.async.cg.shared.global [%0], [%1], 16, %2;\n"
                 :: "r"(dst), "l"(src), "r"(srcsize));
}
__device__ __forceinline__ void cpa8(uint32_t dst, const void* src) {
    asm volatile("cp.async.ca.shared.global [%0], [%1], 8;\n"
                 :: "r"(dst), "l"(src));
}
#define CP_COMMIT() asm volatile("cp.async.commit_group;\n" ::: "memory")
#define CP_WAIT0()  asm volatile("cp.async.wait_group 0;\n" ::: "memory")

// Scratch buffers (allocation-free: static device globals)
__device__ float g_up[(size_t)NB*CF*H*W];
__device__ float g_t1[(size_t)4*NB*KK*H*W];
__device__ float g_t2[(size_t)4*NB*KK*H*W];
__device__ float g_k [(size_t)4*NB*KK*H*W];   // k=0:k1v 1:k1h 2:k2v 3:k2h
// packed weights: [k][grp(3)][ic][tap(9)][ocpair(9)] float2
__device__ float2 g_wp1[(size_t)4*3*CF*81];
__device__ float2 g_wp2[(size_t)4*3*KK*81];
__device__ float2 g_wp3[(size_t)4*3*KK*81];

// ---------------------------------------------------------------------------
__global__ void pack_weights(const float* __restrict__ wgt, float2* __restrict__ wp, int CIN)
{
    int idx = blockIdx.x * blockDim.x + threadIdx.x;
    int total = 4*3*CIN*81;
    if (idx >= total) return;
    int op  = idx % 9;
    int tap = (idx / 9) % 9;
    int ic  = (idx / 81) % CIN;
    int grp = (idx / (81*CIN)) % 3;
    int k   = idx / (81*CIN*3);
    int oc  = grp*18 + 2*op;
    float lo = (oc     < KK) ? wgt[((size_t)(k*KK + oc    )*CIN + ic)*9 + tap] : 0.f;
    float hi = (oc + 1 < KK) ? wgt[((size_t)(k*KK + oc + 1)*CIN + ic)*9 + tap] : 0.f;
    wp[idx] = make_float2(lo, hi);
}

// ---------------------------------------------------------------------------
// 2x bilinear upsample, align_corners=True
// ---------------------------------------------------------------------------
__global__ void upsample_kernel(const float* __restrict__ x, float* __restrict__ out)
{
    int idx = blockIdx.x * blockDim.x + threadIdx.x;
    if (idx >= NB*CF*H*W) return;
    int wo = idx & (W-1);
    int ho = (idx >> 8) & (H-1);
    int bc = idx >> 16;
    const float s = (float)(HH - 1) / (float)(H - 1);
    float py = ho * s;
    float px = wo * s;
    int y0 = (int)floorf(py); int y1 = min(y0 + 1, HH - 1);
    int x0 = (int)floorf(px); int x1 = min(x0 + 1, WHX - 1);
    float wy = py - (float)y0, wx = px - (float)x0;
    const float* p = x + (size_t)bc * HH * WHX;
    float a = p[y0*WHX + x0], b = p[y0*WHX + x1];
    float c = p[y1*WHX + x0], d = p[y1*WHX + x1];
    float top = a*(1.f-wx) + b*wx;
    float bot = c*(1.f-wx) + d*wx;
    out[idx] = top*(1.f-wy) + bot*wy;
}

// ---------------------------------------------------------------------------
// Direct 3x3 conv + bias + relu, packed f32x2 over oc pairs, cp.async staging.
// Block: 64x16 tile, 18 oc (9 pairs), one (k, b, ocg). Thread: 4 px x 9 pairs.
// Input tile: 18 rows x 72 cols (4-aligned halo), double-buffered, 16B cp.async
// with zero-fill for OOB chunks. Weights streamed linearly via 8B cp.async
// from the pre-packed global layout. One barrier + one wait_group per ic.
// grid: (W/64, H/16, 4*NB*3)   [proven-best R5 configuration]
// ---------------------------------------------------------------------------
template<int CIN, bool IN_PER_K>
__global__ void __launch_bounds__(256, 2)
conv3x3_relu3(const float* __restrict__ in, const float2* __restrict__ wpack,
              const float* __restrict__ bias, float* __restrict__ out)
{
    const int OCP = 9;
    const int NGRP = 3;
    const int SROW = 72;
    const int TILE = 18*SROW;
    const int NCHUNK = 18*18;                       // 16B chunks per tile
    const int WOFF = (CIN*162 + 3) & ~3;            // float offset of s_in, 16B aligned

    int z   = blockIdx.z;
    int k   = z / (NB*NGRP);
    int r2  = z % (NB*NGRP);
    int b   = r2 / NGRP;
    int ocg = r2 % NGRP;
    int oc0 = ocg * 18;
    int gx0 = blockIdx.x * 64;
    int gy0 = blockIdx.y * 16;

    extern __shared__ float sm[];
    float2* s_w2 = (float2*)sm;        // [CIN][9][OCP]
    float*  s_in = sm + WOFF;          // [2][18][72]

    int tid = threadIdx.x;
    int tx = tid & 15, ty = tid >> 4;

    // stage packed weights (linear, async)
    {
        const float2* wsrc = wpack + (size_t)(k*NGRP + ocg) * CIN * 81;
        uint32_t wdst = smem_u32(s_w2);
        for (int i = tid; i < CIN*81; i += 256)
            cpa8(wdst + i*8, wsrc + i);
    }

    const float* ip = in + (size_t)(IN_PER_K ? (k*NB + b) : b) * CIN * HW;
    uint32_t sin_base = smem_u32(s_in);

    // prologue: tile for ic=0 into buffer 0
    {
        const float* cp0 = ip;
        for (int i = tid; i < NCHUNK; i += 256) {
            int rr = i / 18, f = i % 18;
            int gy = gy0 - 1 + rr;
            int gx = gx0 - 4 + 4*f;
            bool ok = ((unsigned)gy < H) && (gx >= 0) && (gx < W);
            const float* src = ok ? (cp0 + gy*W + gx) : cp0;
            cpa16(sin_base + (rr*SROW + f*4)*4, src, ok ? 16 : 0);
        }
    }
    CP_COMMIT();

    ull acc[OCP][4];
    #pragma unroll
    for (int o = 0; o < OCP; o++)
        #pragma unroll
        for (int p = 0; p < 4; p++) acc[o][p] = 0ULL;

    for (int ic = 0; ic < CIN; ic++) {
        CP_WAIT0();
        __syncthreads();

        // prefetch next tile into the other buffer
        if (ic + 1 < CIN) {
            const float* cp1 = ip + (size_t)(ic+1)*HW;
            uint32_t dst = sin_base + ((ic+1)&1)*TILE*4;
            for (int i = tid; i < NCHUNK; i += 256) {
                int rr = i / 18, f = i % 18;
                int gy = gy0 - 1 + rr;
                int gx = gx0 - 4 + 4*f;
                bool ok = ((unsigned)gy < H) && (gx >= 0) && (gx < W);
                const float* src = ok ? (cp1 + gy*W + gx) : cp1;
                cpa16(dst + (rr*SROW + f*4)*4, src, ok ? 16 : 0);
            }
            CP_COMMIT();
        }

        const float* sb = s_in + (ic&1)*TILE;
        const ull* wq = (const ull*)s_w2 + (size_t)ic*81;

        #pragma unroll
        for (int r = 0; r < 3; r++) {
            const float* rowp = sb + (ty + r)*SROW + tx*4 + 3;
            ull vr[6];
            #pragma unroll
            for (int c2 = 0; c2 < 6; c2++) {
                float v = rowp[c2];
                vr[c2] = pack2(v, v);
            }
            #pragma unroll
            for (int op = 0; op < OCP; op++) {
                ull w0 = wq[(r*3 + 0)*OCP + op];
                ull w1 = wq[(r*3 + 1)*OCP + op];
                ull w2 = wq[(r*3 + 2)*OCP + op];
                #pragma unroll
                for (int p = 0; p < 4; p++) {
                    acc[op][p] = ffma2(w0, vr[p],   acc[op][p]);
                    acc[op][p] = ffma2(w1, vr[p+1], acc[op][p]);
                    acc[op][p] = ffma2(w2, vr[p+2], acc[op][p]);
                }
            }
        }
    }

    // epilogue: bias + relu + store
    float* outp = out + (size_t)(k*NB + b) * KK * HW;
    int oy = gy0 + ty, ox = gx0 + tx*4;
    #pragma unroll
    for (int opi = 0; opi < OCP; opi++) {
        float lo[4], hi[4];
        #pragma unroll
        for (int p = 0; p < 4; p++) unpack2(acc[opi][p], lo[p], hi[p]);
        int oc = oc0 + 2*opi;
        if (oc < KK) {
            float bv = bias[k*KK + oc];
            float4 v4;
            v4.x = fmaxf(lo[0] + bv, 0.f);
            v4.y = fmaxf(lo[1] + bv, 0.f);
            v4.z = fmaxf(lo[2] + bv, 0.f);
            v4.w = fmaxf(lo[3] + bv, 0.f);
            *(float4*)(outp + (size_t)oc*HW + oy*W + ox) = v4;
        }
        if (oc + 1 < KK) {
            float bv = bias[k*KK + oc + 1];
            float4 v4;
            v4.x = fmaxf(hi[0] + bv, 0.f);
            v4.y = fmaxf(hi[1] + bv, 0.f);
            v4.z = fmaxf(hi[2] + bv, 0.f);
            v4.w = fmaxf(hi[3] + bv, 0.f);
            *(float4*)(outp + (size_t)(oc+1)*HW + oy*W + ox) = v4;
        }
    }
}

// ---------------------------------------------------------------------------
// Adaptive separable conv, 2 vertically adjacent outputs per thread sharing
// the row-window LDS. Packed f32x2 over taps with parity phase.
// grid: (W/32, H/16, NB), block (32, 8). Tile 32x16 outputs, 66-row smem.
// ---------------------------------------------------------------------------
__global__ void __launch_bounds__(256)
sepconv3_kernel(const float* __restrict__ i1, const float* __restrict__ i2,
                const float* __restrict__ gk, float* __restrict__ out)
{
    const int SW = 84;
    int b   = blockIdx.z;
    int gx0 = blockIdx.x * 32;
    int gy0 = blockIdx.y * 16;
    int tx  = threadIdx.x, ty = threadIdx.y;
    int tid = ty * 32 + tx;
    int x  = gx0 + tx;
    int y0 = gy0 + 2*ty;
    int q = tx & 1;
    int col0 = tx - q;

    __shared__ __align__(16) float s_img[66 * SW];

    float accA[3] = {0.f, 0.f, 0.f};
    float accB[3] = {0.f, 0.f, 0.f};

    #pragma unroll 1
    for (int im = 0; im < 2; im++) {
        const float* ip   = im ? i2 : i1;
        const float* kvp0 = gk + (((size_t)(im*2 + 0)*NB + b)*KK)*HW + (size_t)y0*W + x;
        const float* kvp1 = kvp0 + W;
        const float* khp0 = gk + (((size_t)(im*2 + 1)*NB + b)*KK)*HW + (size_t)y0*W + x;
        const float* khp1 = khp0 + W;

        ull KP0[26], KP1[26];
        #pragma unroll
        for (int m = 0; m < 26; m++) {
            int t0 = 2*m - q, t1 = 2*m + 1 - q;
            float a0 = ((unsigned)t0 < KK) ? khp0[(size_t)t0 * HW] : 0.f;
            float a1 = ((unsigned)t1 < KK) ? khp0[(size_t)t1 * HW] : 0.f;
            KP0[m] = pack2(a0, a1);
            float b0 = ((unsigned)t0 < KK) ? khp1[(size_t)t0 * HW] : 0.f;
            float b1 = ((unsigned)t1 < KK) ? khp1[(size_t)t1 * HW] : 0.f;
            KP1[m] = pack2(b0, b1);
        }

        #pragma unroll 1
        for (int c = 0; c < 3; c++) {
            const float* cp = ip + ((size_t)b*3 + c) * HP * WPP;
            __syncthreads();
            for (int i = tid; i < 66*SW; i += 256) {
                int rr = i / SW, cc = i % SW;
                s_img[i] = (cc < 82) ? cp[(size_t)(gy0 + rr)*WPP + gx0 + cc] : 0.f;
            }
            __syncthreads();

            ull A0 = 0ULL, A1 = 0ULL;
            #pragma unroll 1
            for (int t = 0; t < 52; t++) {
                const ull* rp = (const ull*)(s_img + (2*ty + t)*SW + col0);
                ull hs0 = 0ULL, hs1 = 0ULL;
                #pragma unroll
                for (int m = 0; m < 26; m++) {
                    ull v = rp[m];
                    hs0 = ffma2(KP0[m], v, hs0);
                    hs1 = ffma2(KP1[m], v, hs1);
                }
                if (t < 51) {
                    float kv = kvp0[(size_t)t * HW];
                    A0 = ffma2(pack2(kv, kv), hs0, A0);
                }
                if (t >= 1) {
                    float kv = kvp1[(size_t)(t-1) * HW];
                    A1 = ffma2(pack2(kv, kv), hs1, A1);
                }
            }
            float lo, hi;
            unpack2(A0, lo, hi); accA[c] += lo + hi;
            unpack2(A1, lo, hi); accB[c] += lo + hi;
        }
    }

    size_t ob0 = ((size_t)b*3)*HW + (size_t)y0*W + x;
    size_t ob1 = ob0 + W;
    out[ob0]        = accA[0];
    out[ob0 + HW]   = accA[1];
    out[ob0 + 2*HW] = accA[2];
    out[ob1]        = accB[0];
    out[ob1 + HW]   = accB[1];
    out[ob1 + 2*HW] = accB[2];
}

// ---------------------------------------------------------------------------
extern "C" void kernel_launch(void* const* d_in, const int* in_sizes, int n_in,
                              void* d_out, int out_size)
{
    const float* x  = (const float*)d_in[0];
    const float* i1 = (const float*)d_in[1];
    const float* i2 = (const float*)d_in[2];
    const float* W1 = (const float*)d_in[3];
    const float* B1 = (const float*)d_in[4];
    const float* W2 = (const float*)d_in[5];
    const float* B2 = (const float*)d_in[6];
    const float* W3 = (const float*)d_in[7];
    const float* B3 = (const float*)d_in[8];
    float* out = (float*)d_out;

    float* up = nullptr; float* t1 = nullptr; float* t2 = nullptr; float* kk = nullptr;
    float2* wp1 = nullptr; float2* wp2 = nullptr; float2* wp3 = nullptr;
    cudaGetSymbolAddress((void**)&up, g_up);
    cudaGetSymbolAddress((void**)&t1, g_t1);
    cudaGetSymbolAddress((void**)&t2, g_t2);
    cudaGetSymbolAddress((void**)&kk, g_k);
    cudaGetSymbolAddress((void**)&wp1, g_wp1);
    cudaGetSymbolAddress((void**)&wp2, g_wp2);
    cudaGetSymbolAddress((void**)&wp3, g_wp3);

    const int WOFF64 = (64*162 + 3) & ~3;
    const int WOFF51 = (51*162 + 3) & ~3;
    size_t smem64 = (size_t)(WOFF64 + 2*18*72) * sizeof(float);
    size_t smem51 = (size_t)(WOFF51 + 2*18*72) * sizeof(float);
    cudaFuncSetAttribute(conv3x3_relu3<64, false>,
                         cudaFuncAttributeMaxDynamicSharedMemorySize, (int)smem64);
    cudaFuncSetAttribute(conv3x3_relu3<51, true>,
                         cudaFuncAttributeMaxDynamicSharedMemorySize, (int)smem51);

    // 0) pack weights (tiny)
    {
        int t64 = 4*3*64*81, t51 = 4*3*51*81;
        pack_weights<<<(t64 + 255)/256, 256>>>(W1, wp1, 64);
        pack_weights<<<(t51 + 255)/256, 256>>>(W2, wp2, 51);
        pack_weights<<<(t51 + 255)/256, 256>>>(W3, wp3, 51);
    }

    // 1) upsample features
    {
        int n = NB*CF*H*W;
        upsample_kernel<<<(n + 255)/256, 256>>>(x, up);
    }

    // 2) three conv stages
    dim3 cgrid(W/64, H/16, 4*NB*3);
    conv3x3_relu3<64, false><<<cgrid, 256, smem64>>>(up, wp1, B1, t1);
    conv3x3_relu3<51, true ><<<cgrid, 256, smem51>>>(t1, wp2, B2, t2);
    conv3x3_relu3<51, true ><<<cgrid, 256, smem51>>>(t2, wp3, B3, kk);

    // 3) separable filtering of both images + sum
    {
        dim3 g(W/32, H/16, NB);
        dim3 blk(32, 8);
        sepconv3_kernel<<<g, blk>>>(i1, i2, kk, out);
    }
}

// round 10
// speedup vs baseline: 1.3427x; 1.1328x over previous
#include <cuda_runtime.h>
#include <cstdint>

#define HH 128
#define WHX 128
#define H 256
#define W 256
#define NB 4
#define CF 64
#define KK 51
#define PADK 25
#define HP (H + 2*PADK)   // 306
#define WPP (W + 2*PADK)  // 306
#define HW (H*W)          // 65536

typedef unsigned long long ull;

__device__ __forceinline__ ull pack2(float lo, float hi) {
    ull r; asm("mov.b64 %0, {%1, %2};" : "=l"(r) : "f"(lo), "f"(hi)); return r;
}
__device__ __forceinline__ void unpack2(ull v, float& lo, float& hi) {
    asm("mov.b64 {%0, %1}, %2;" : "=f"(lo), "=f"(hi) : "l"(v));
}
__device__ __forceinline__ ull ffma2(ull a, ull b, ull c) {
    ull d; asm("fma.rn.f32x2 %0, %1, %2, %3;" : "=l"(d) : "l"(a), "l"(b), "l"(c)); return d;
}
__device__ __forceinline__ uint32_t smem_u32(const void* p) {
    return (uint32_t)__cvta_generic_to_shared(p);
}
__device__ __forceinline__ void cpa16(uint32_t dst, const void* src, int srcsize) {
    asm volatile("cp.async.cg.shared.global [%0], [%1], 16, %2;\n"
                 :: "r"(dst), "l"(src), "r"(srcsize));
}
__device__ __forceinline__ void cpa8(uint32_t dst, const void* src) {
    asm volatile("cp.async.ca.shared.global [%0], [%1], 8;\n"
                 :: "r"(dst), "l"(src));
}
#define CP_COMMIT() asm volatile("cp.async.commit_group;\n" ::: "memory")
#define CP_WAIT0()  asm volatile("cp.async.wait_group 0;\n" ::: "memory")

// Scratch buffers (allocation-free: static device globals)
__device__ float g_up[(size_t)NB*CF*H*W];
__device__ float g_t1[(size_t)4*NB*KK*H*W];
__device__ float g_t2[(size_t)4*NB*KK*H*W];
__device__ float g_k [(size_t)4*NB*KK*H*W];   // k=0:k1v 1:k1h 2:k2v 3:k2h
// packed weights: [k][grp(3)][ic][tap(9)][ocpair(9)] float2
__device__ float2 g_wp1[(size_t)4*3*CF*81];
__device__ float2 g_wp2[(size_t)4*3*KK*81];
__device__ float2 g_wp3[(size_t)4*3*KK*81];

// ---------------------------------------------------------------------------
__global__ void pack_weights(const float* __restrict__ wgt, float2* __restrict__ wp, int CIN)
{
    int idx = blockIdx.x * blockDim.x + threadIdx.x;
    int total = 4*3*CIN*81;
    if (idx >= total) return;
    int op  = idx % 9;
    int tap = (idx / 9) % 9;
    int ic  = (idx / 81) % CIN;
    int grp = (idx / (81*CIN)) % 3;
    int k   = idx / (81*CIN*3);
    int oc  = grp*18 + 2*op;
    float lo = (oc     < KK) ? wgt[((size_t)(k*KK + oc    )*CIN + ic)*9 + tap] : 0.f;
    float hi = (oc + 1 < KK) ? wgt[((size_t)(k*KK + oc + 1)*CIN + ic)*9 + tap] : 0.f;
    wp[idx] = make_float2(lo, hi);
}

// ---------------------------------------------------------------------------
// 2x bilinear upsample, align_corners=True
// ---------------------------------------------------------------------------
__global__ void upsample_kernel(const float* __restrict__ x, float* __restrict__ out)
{
    int idx = blockIdx.x * blockDim.x + threadIdx.x;
    if (idx >= NB*CF*H*W) return;
    int wo = idx & (W-1);
    int ho = (idx >> 8) & (H-1);
    int bc = idx >> 16;
    const float s = (float)(HH - 1) / (float)(H - 1);
    float py = ho * s;
    float px = wo * s;
    int y0 = (int)floorf(py); int y1 = min(y0 + 1, HH - 1);
    int x0 = (int)floorf(px); int x1 = min(x0 + 1, WHX - 1);
    float wy = py - (float)y0, wx = px - (float)x0;
    const float* p = x + (size_t)bc * HH * WHX;
    float a = p[y0*WHX + x0], b = p[y0*WHX + x1];
    float c = p[y1*WHX + x0], d = p[y1*WHX + x1];
    float top = a*(1.f-wx) + b*wx;
    float bot = c*(1.f-wx) + d*wx;
    out[idx] = top*(1.f-wy) + bot*wy;
}

// ---------------------------------------------------------------------------
// Direct 3x3 conv + bias + relu, packed f32x2 over oc pairs, cp.async staging.
// R5 structure with the channel loop unrolled by 2: each pipeline stage
// stages TWO input-channel tiles, so barrier/wait/staging overhead per FFMA2
// halves. Value loads per row: 1 x LDS.128 + 2 x LDS.32.
// grid: (W/64, H/16, 4*NB*3), block 256 (tx=tid&15 -> 4 px, ty=tid>>4)
// ---------------------------------------------------------------------------
template<int CIN, bool IN_PER_K>
__global__ void __launch_bounds__(256, 2)
conv3x3_relu5(const float* __restrict__ in, const float2* __restrict__ wpack,
              const float* __restrict__ bias, float* __restrict__ out)
{
    const int OCP = 9;
    const int NGRP = 3;
    const int SROW = 72;
    const int TILE = 18*SROW;                 // one channel tile (1296 floats)
    const int NCHUNK = 18*18;                 // 16B chunks per tile
    const int NPAIR = (CIN + 1) / 2;
    const int WOFF = (CIN*162 + 3) & ~3;      // float offset of s_in, 16B aligned

    int z   = blockIdx.z;
    int k   = z / (NB*NGRP);
    int r2  = z % (NB*NGRP);
    int b   = r2 / NGRP;
    int ocg = r2 % NGRP;
    int oc0 = ocg * 18;
    int gx0 = blockIdx.x * 64;
    int gy0 = blockIdx.y * 16;

    extern __shared__ float sm[];
    float2* s_w2 = (float2*)sm;        // [CIN][9][OCP]
    float*  s_in = sm + WOFF;          // [2 buf][2 ch][18][72]

    int tid = threadIdx.x;
    int tx = tid & 15, ty = tid >> 4;

    // stage packed weights (linear, async; rides along with first group)
    {
        const float2* wsrc = wpack + (size_t)(k*NGRP + ocg) * CIN * 81;
        uint32_t wdst = smem_u32(s_w2);
        for (int i = tid; i < CIN*81; i += 256)
            cpa8(wdst + i*8, wsrc + i);
    }

    const float* ip = in + (size_t)(IN_PER_K ? (k*NB + b) : b) * CIN * HW;
    uint32_t sin_base = smem_u32(s_in);

    // stage channel pair j (tiles 2j, 2j+1) into buffer (j&1); commits group
    auto stage = [&](int j) {
        int nch = (2*j + 2 <= CIN) ? 2 : 1;
        uint32_t dstb = sin_base + (j & 1) * (2*TILE) * 4;
        for (int s = 0; s < nch; s++) {
            const float* cp = ip + (size_t)(2*j + s) * HW;
            uint32_t dst = dstb + s*TILE*4;
            for (int i = tid; i < NCHUNK; i += 256) {
                int rr = i / 18, f = i % 18;
                int gy = gy0 - 1 + rr;
                int gx = gx0 - 4 + 4*f;
                bool ok = ((unsigned)gy < H) && (gx >= 0) && (gx < W);
                cpa16(dst + (rr*SROW + f*4)*4, ok ? (cp + gy*W + gx) : cp, ok ? 16 : 0);
            }
        }
        CP_COMMIT();
    };

    stage(0);

    ull acc[OCP][4];
    #pragma unroll
    for (int o = 0; o < OCP; o++)
        #pragma unroll
        for (int p = 0; p < 4; p++) acc[o][p] = 0ULL;

    #pragma unroll 1
    for (int j = 0; j < NPAIR; j++) {
        CP_WAIT0();
        __syncthreads();
        if (j + 1 < NPAIR) stage(j + 1);

        int nch = (2*j + 2 <= CIN) ? 2 : 1;
        const float* buf = s_in + (j & 1) * (2*TILE);

        #pragma unroll 1
        for (int s = 0; s < nch; s++) {
            const float* sb = buf + s*TILE;
            const ull* wq = (const ull*)s_w2 + (size_t)(2*j + s)*81;

            #pragma unroll
            for (int r = 0; r < 3; r++) {
                const float* rowp = sb + (ty + r)*SROW + tx*4 + 3;
                float e0 = rowp[0];
                float4 m4 = *(const float4*)(rowp + 1);   // 16B-aligned
                float e5 = rowp[5];
                ull vr[6];
                vr[0] = pack2(e0,   e0);
                vr[1] = pack2(m4.x, m4.x);
                vr[2] = pack2(m4.y, m4.y);
                vr[3] = pack2(m4.z, m4.z);
                vr[4] = pack2(m4.w, m4.w);
                vr[5] = pack2(e5,   e5);
                #pragma unroll
                for (int op = 0; op < OCP; op++) {
                    ull w0 = wq[(r*3 + 0)*OCP + op];
                    ull w1 = wq[(r*3 + 1)*OCP + op];
                    ull w2 = wq[(r*3 + 2)*OCP + op];
                    #pragma unroll
                    for (int p = 0; p < 4; p++) {
                        acc[op][p] = ffma2(w0, vr[p],   acc[op][p]);
                        acc[op][p] = ffma2(w1, vr[p+1], acc[op][p]);
                        acc[op][p] = ffma2(w2, vr[p+2], acc[op][p]);
                    }
                }
            }
        }
    }

    // epilogue: bias + relu + store
    float* outp = out + (size_t)(k*NB + b) * KK * HW;
    int oy = gy0 + ty, ox = gx0 + tx*4;
    #pragma unroll
    for (int opi = 0; opi < OCP; opi++) {
        float lo[4], hi[4];
        #pragma unroll
        for (int p = 0; p < 4; p++) unpack2(acc[opi][p], lo[p], hi[p]);
        int oc = oc0 + 2*opi;
        if (oc < KK) {
            float bv = bias[k*KK + oc];
            float4 v4;
            v4.x = fmaxf(lo[0] + bv, 0.f);
            v4.y = fmaxf(lo[1] + bv, 0.f);
            v4.z = fmaxf(lo[2] + bv, 0.f);
            v4.w = fmaxf(lo[3] + bv, 0.f);
            *(float4*)(outp + (size_t)oc*HW + oy*W + ox) = v4;
        }
        if (oc + 1 < KK) {
            float bv = bias[k*KK + oc + 1];
            float4 v4;
            v4.x = fmaxf(hi[0] + bv, 0.f);
            v4.y = fmaxf(hi[1] + bv, 0.f);
            v4.z = fmaxf(hi[2] + bv, 0.f);
            v4.w = fmaxf(hi[3] + bv, 0.f);
            *(float4*)(outp + (size_t)(oc+1)*HW + oy*W + ox) = v4;
        }
    }
}

// ---------------------------------------------------------------------------
// Adaptive separable conv (R5-proven version): 1 output px per thread,
// packed f32x2 over taps with parity phase. grid: (W/32, H/8, NB), block (32,8)
// ---------------------------------------------------------------------------
__global__ void __launch_bounds__(256)
sepconv2_kernel(const float* __restrict__ i1, const float* __restrict__ i2,
                const float* __restrict__ gk, float* __restrict__ out)
{
    const int SW = 84;
    int b   = blockIdx.z;
    int gx0 = blockIdx.x * 32;
    int gy0 = blockIdx.y * 8;
    int tx  = threadIdx.x, ty = threadIdx.y;
    int tid = ty * 32 + tx;
    int y = gy0 + ty, x = gx0 + tx;
    int q = tx & 1;
    int col0 = tx - q;

    __shared__ __align__(16) float s_img[58 * SW];

    float acc[3] = {0.f, 0.f, 0.f};

    #pragma unroll 1
    for (int im = 0; im < 2; im++) {
        const float* ip  = im ? i2 : i1;
        const float* kvp = gk + (((size_t)(im*2 + 0)*NB + b)*KK)*HW + (size_t)y*W + x;
        const float* khp = gk + (((size_t)(im*2 + 1)*NB + b)*KK)*HW + (size_t)y*W + x;

        ull KP[26];
        #pragma unroll
        for (int m = 0; m < 26; m++) {
            int t0 = 2*m - q, t1 = 2*m + 1 - q;
            float lo = ((unsigned)t0 < KK) ? khp[(size_t)t0 * HW] : 0.f;
            float hi = ((unsigned)t1 < KK) ? khp[(size_t)t1 * HW] : 0.f;
            KP[m] = pack2(lo, hi);
        }

        #pragma unroll 1
        for (int c = 0; c < 3; c++) {
            const float* cp = ip + ((size_t)b*3 + c) * HP * WPP;
            __syncthreads();
            for (int i = tid; i < 58*SW; i += 256) {
                int rr = i / SW, cc = i % SW;
                s_img[i] = (cc < 82) ? cp[(size_t)(gy0 + rr)*WPP + gx0 + cc] : 0.f;
            }
            __syncthreads();

            ull acc2 = 0ULL;
            #pragma unroll 1
            for (int i = 0; i < KK; i++) {
                const ull* rp = (const ull*)(s_img + (ty + i)*SW + col0);
                ull hs = 0ULL;
                #pragma unroll
                for (int m = 0; m < 26; m++) hs = ffma2(KP[m], rp[m], hs);
                float kv = kvp[(size_t)i * HW];
                acc2 = ffma2(pack2(kv, kv), hs, acc2);
            }
            float lo, hi; unpack2(acc2, lo, hi);
            acc[c] += lo + hi;
        }
    }

    size_t ob = ((size_t)b*3)*HW + (size_t)y*W + x;
    out[ob]        = acc[0];
    out[ob + HW]   = acc[1];
    out[ob + 2*HW] = acc[2];
}

// ---------------------------------------------------------------------------
extern "C" void kernel_launch(void* const* d_in, const int* in_sizes, int n_in,
                              void* d_out, int out_size)
{
    const float* x  = (const float*)d_in[0];
    const float* i1 = (const float*)d_in[1];
    const float* i2 = (const float*)d_in[2];
    const float* W1 = (const float*)d_in[3];
    const float* B1 = (const float*)d_in[4];
    const float* W2 = (const float*)d_in[5];
    const float* B2 = (const float*)d_in[6];
    const float* W3 = (const float*)d_in[7];
    const float* B3 = (const float*)d_in[8];
    float* out = (float*)d_out;

    float* up = nullptr; float* t1 = nullptr; float* t2 = nullptr; float* kk = nullptr;
    float2* wp1 = nullptr; float2* wp2 = nullptr; float2* wp3 = nullptr;
    cudaGetSymbolAddress((void**)&up, g_up);
    cudaGetSymbolAddress((void**)&t1, g_t1);
    cudaGetSymbolAddress((void**)&t2, g_t2);
    cudaGetSymbolAddress((void**)&kk, g_k);
    cudaGetSymbolAddress((void**)&wp1, g_wp1);
    cudaGetSymbolAddress((void**)&wp2, g_wp2);
    cudaGetSymbolAddress((void**)&wp3, g_wp3);

    const int WOFF64 = (64*162 + 3) & ~3;
    const int WOFF51 = (51*162 + 3) & ~3;
    size_t smem64 = (size_t)(WOFF64 + 4*18*72) * sizeof(float);
    size_t smem51 = (size_t)(WOFF51 + 4*18*72) * sizeof(float);
    cudaFuncSetAttribute(conv3x3_relu5<64, false>,
                         cudaFuncAttributeMaxDynamicSharedMemorySize, (int)smem64);
    cudaFuncSetAttribute(conv3x3_relu5<51, true>,
                         cudaFuncAttributeMaxDynamicSharedMemorySize, (int)smem51);

    // 0) pack weights (tiny)
    {
        int t64 = 4*3*64*81, t51 = 4*3*51*81;
        pack_weights<<<(t64 + 255)/256, 256>>>(W1, wp1, 64);
        pack_weights<<<(t51 + 255)/256, 256>>>(W2, wp2, 51);
        pack_weights<<<(t51 + 255)/256, 256>>>(W3, wp3, 51);
    }

    // 1) upsample features
    {
        int n = NB*CF*H*W;
        upsample_kernel<<<(n + 255)/256, 256>>>(x, up);
    }

    // 2) three conv stages
    dim3 cgrid(W/64, H/16, 4*NB*3);
    conv3x3_relu5<64, false><<<cgrid, 256, smem64>>>(up, wp1, B1, t1);
    conv3x3_relu5<51, true ><<<cgrid, 256, smem51>>>(t1, wp2, B2, t2);
    conv3x3_relu5<51, true ><<<cgrid, 256, smem51>>>(t2, wp3, B3, kk);

    // 3) separable filtering of both images + sum
    {
        dim3 g(W/32, H/8, NB);
        dim3 blk(32, 8);
        sepconv2_kernel<<<g, blk>>>(i1, i2, kk, out);
    }
}

// round 12
// speedup vs baseline: 1.3839x; 1.0307x over previous
#include <cuda_runtime.h>
#include <cstdint>

#define HH 128
#define WHX 128
#define H 256
#define W 256
#define NB 4
#define CF 64
#define KK 51
#define PADK 25
#define HP (H + 2*PADK)   // 306
#define WPP (W + 2*PADK)  // 306
#define HW (H*W)          // 65536

typedef unsigned long long ull;

__device__ __forceinline__ ull pack2(float lo, float hi) {
    ull r; asm("mov.b64 %0, {%1, %2};" : "=l"(r) : "f"(lo), "f"(hi)); return r;
}
__device__ __forceinline__ void unpack2(ull v, float& lo, float& hi) {
    asm("mov.b64 {%0, %1}, %2;" : "=f"(lo), "=f"(hi) : "l"(v));
}
__device__ __forceinline__ ull ffma2(ull a, ull b, ull c) {
    ull d; asm("fma.rn.f32x2 %0, %1, %2, %3;" : "=l"(d) : "l"(a), "l"(b), "l"(c)); return d;
}
__device__ __forceinline__ uint32_t smem_u32(const void* p) {
    return (uint32_t)__cvta_generic_to_shared(p);
}
__device__ __forceinline__ void cpa16(uint32_t dst, const void* src, int srcsize) {
    asm volatile("cp.async.cg.shared.global [%0], [%1], 16, %2;\n"
                 :: "r"(dst), "l"(src), "r"(srcsize));
}
__device__ __forceinline__ void cpa8(uint32_t dst, const void* src) {
    asm volatile("cp.async.ca.shared.global [%0], [%1], 8;\n"
                 :: "r"(dst), "l"(src));
}
#define CP_COMMIT() asm volatile("cp.async.commit_group;\n" ::: "memory")
#define CP_WAIT0()  asm volatile("cp.async.wait_group 0;\n" ::: "memory")

// Scratch buffers (allocation-free: static device globals)
__device__ float g_up[(size_t)NB*CF*H*W];
__device__ float g_t1[(size_t)4*NB*KK*H*W];
__device__ float g_t2[(size_t)4*NB*KK*H*W];
__device__ float g_k [(size_t)4*NB*KK*H*W];   // k=0:k1v 1:k1h 2:k2v 3:k2h
// packed weights: [k][grp(3)][ic][tap(9)][10 ocpairs] float2 (pair 9 = pad)
__device__ float2 g_wp1[(size_t)4*3*CF*90];
__device__ float2 g_wp2[(size_t)4*3*KK*90];
__device__ float2 g_wp3[(size_t)4*3*KK*90];

// ---------------------------------------------------------------------------
__global__ void pack_weights(const float* __restrict__ wgt, float2* __restrict__ wp, int CIN)
{
    int idx = blockIdx.x * blockDim.x + threadIdx.x;
    int total = 4*3*CIN*90;
    if (idx >= total) return;
    int op  = idx % 10;
    int tap = (idx / 10) % 9;
    int ic  = (idx / 90) % CIN;
    int grp = (idx / (90*CIN)) % 3;
    int k   = idx / (90*CIN*3);
    float lo = 0.f, hi = 0.f;
    if (op < 9) {
        int oc = grp*18 + 2*op;
        if (oc     < KK) lo = wgt[((size_t)(k*KK + oc    )*CIN + ic)*9 + tap];
        if (oc + 1 < KK) hi = wgt[((size_t)(k*KK + oc + 1)*CIN + ic)*9 + tap];
    }
    wp[idx] = make_float2(lo, hi);
}

// ---------------------------------------------------------------------------
// 2x bilinear upsample, align_corners=True
// ---------------------------------------------------------------------------
__global__ void upsample_kernel(const float* __restrict__ x, float* __restrict__ out)
{
    int idx = blockIdx.x * blockDim.x + threadIdx.x;
    if (idx >= NB*CF*H*W) return;
    int wo = idx & (W-1);
    int ho = (idx >> 8) & (H-1);
    int bc = idx >> 16;
    const float s = (float)(HH - 1) / (float)(H - 1);
    float py = ho * s;
    float px = wo * s;
    int y0 = (int)floorf(py); int y1 = min(y0 + 1, HH - 1);
    int x0 = (int)floorf(px); int x1 = min(x0 + 1, WHX - 1);
    float wy = py - (float)y0, wx = px - (float)x0;
    const float* p = x + (size_t)bc * HH * WHX;
    float a = p[y0*WHX + x0], b = p[y0*WHX + x1];
    float c = p[y1*WHX + x0], d = p[y1*WHX + x1];
    float top = a*(1.f-wx) + b*wx;
    float bot = c*(1.f-wx) + d*wx;
    out[idx] = top*(1.f-wy) + bot*wy;
}

// ---------------------------------------------------------------------------
// Direct 3x3 conv + bias + relu, packed f32x2 over oc pairs, cp.async staging.
// Channel loop unrolled by 2 (R10). Weight loads paired: per tap the 9 pairs
// come in as 4 x LDS.128 + 1 x LDS.64 (16B-aligned [tap][10] layout) -> weight
// issue count per ic drops 81 -> 45. FFMA2 count unchanged.
// grid: (W/64, H/16, 4*NB*3), block 256 (tx=tid&15 -> 4 px, ty=tid>>4)
// ---------------------------------------------------------------------------
template<int CIN, bool IN_PER_K>
__global__ void __launch_bounds__(256, 2)
conv3x3_relu6(const float* __restrict__ in, const float2* __restrict__ wpack,
              const float* __restrict__ bias, float* __restrict__ out)
{
    const int OCP = 9;
    const int NGRP = 3;
    const int SROW = 72;
    const int TILE = 18*SROW;                 // one channel tile (1296 floats)
    const int NCHUNK = 18*18;                 // 16B chunks per tile
    const int NPAIR = (CIN + 1) / 2;
    const int WOFF = CIN*180;                 // float offset of s_in (16B aligned)

    int z   = blockIdx.z;
    int k   = z / (NB*NGRP);
    int r2  = z % (NB*NGRP);
    int b   = r2 / NGRP;
    int ocg = r2 % NGRP;
    int oc0 = ocg * 18;
    int gx0 = blockIdx.x * 64;
    int gy0 = blockIdx.y * 16;

    extern __shared__ __align__(16) float sm[];
    float2* s_w2 = (float2*)sm;        // [CIN][9][10]
    float*  s_in = sm + WOFF;          // [2 buf][2 ch][18][72]

    int tid = threadIdx.x;
    int tx = tid & 15, ty = tid >> 4;

    // stage packed weights (linear, async; rides along with first group)
    {
        const float2* wsrc = wpack + (size_t)(k*NGRP + ocg) * CIN * 90;
        uint32_t wdst = smem_u32(s_w2);
        for (int i = tid; i < CIN*90; i += 256)
            cpa8(wdst + i*8, wsrc + i);
    }

    const float* ip = in + (size_t)(IN_PER_K ? (k*NB + b) : b) * CIN * HW;
    uint32_t sin_base = smem_u32(s_in);

    // stage channel pair j (tiles 2j, 2j+1) into buffer (j&1); commits group
    auto stage = [&](int j) {
        int nch = (2*j + 2 <= CIN) ? 2 : 1;
        uint32_t dstb = sin_base + (j & 1) * (2*TILE) * 4;
        for (int s = 0; s < nch; s++) {
            const float* cp = ip + (size_t)(2*j + s) * HW;
            uint32_t dst = dstb + s*TILE*4;
            for (int i = tid; i < NCHUNK; i += 256) {
                int rr = i / 18, f = i % 18;
                int gy = gy0 - 1 + rr;
                int gx = gx0 - 4 + 4*f;
                bool ok = ((unsigned)gy < H) && (gx >= 0) && (gx < W);
                cpa16(dst + (rr*SROW + f*4)*4, ok ? (cp + gy*W + gx) : cp, ok ? 16 : 0);
            }
        }
        CP_COMMIT();
    };

    stage(0);

    ull acc[OCP][4];
    #pragma unroll
    for (int o = 0; o < OCP; o++)
        #pragma unroll
        for (int p = 0; p < 4; p++) acc[o][p] = 0ULL;

    #pragma unroll 1
    for (int j = 0; j < NPAIR; j++) {
        CP_WAIT0();
        __syncthreads();
        if (j + 1 < NPAIR) stage(j + 1);

        int nch = (2*j + 2 <= CIN) ? 2 : 1;
        const float* buf = s_in + (j & 1) * (2*TILE);

        #pragma unroll 1
        for (int s = 0; s < nch; s++) {
            const float* sb = buf + s*TILE;
            const ull* wq = (const ull*)s_w2 + (size_t)(2*j + s)*90;

            #pragma unroll
            for (int r = 0; r < 3; r++) {
                const float* rowp = sb + (ty + r)*SROW + tx*4 + 3;
                float e0 = rowp[0];
                float4 m4 = *(const float4*)(rowp + 1);   // 16B-aligned
                float e5 = rowp[5];
                ull vr[6];
                vr[0] = pack2(e0,   e0);
                vr[1] = pack2(m4.x, m4.x);
                vr[2] = pack2(m4.y, m4.y);
                vr[3] = pack2(m4.z, m4.z);
                vr[4] = pack2(m4.w, m4.w);
                vr[5] = pack2(e5,   e5);

                #pragma unroll
                for (int tc = 0; tc < 3; tc++) {
                    const ull* wt = wq + (r*3 + tc)*10;   // tap base, 16B aligned (80 B/tap)
                    ulonglong2 b0 = *(const ulonglong2*)(wt + 0);  // pairs 0,1
                    ulonglong2 b1 = *(const ulonglong2*)(wt + 2);  // pairs 2,3
                    ulonglong2 b2 = *(const ulonglong2*)(wt + 4);  // pairs 4,5
                    ulonglong2 b3 = *(const ulonglong2*)(wt + 6);  // pairs 6,7
                    ull w8 = wt[8];
                    ull w[9] = { b0.x, b0.y, b1.x, b1.y, b2.x, b2.y, b3.x, b3.y, w8 };
                    #pragma unroll
                    for (int op = 0; op < OCP; op++) {
                        #pragma unroll
                        for (int p = 0; p < 4; p++)
                            acc[op][p] = ffma2(w[op], vr[p + tc], acc[op][p]);
                    }
                }
            }
        }
    }

    // epilogue: bias + relu + store
    float* outp = out + (size_t)(k*NB + b) * KK * HW;
    int oy = gy0 + ty, ox = gx0 + tx*4;
    #pragma unroll
    for (int opi = 0; opi < OCP; opi++) {
        float lo[4], hi[4];
        #pragma unroll
        for (int p = 0; p < 4; p++) unpack2(acc[opi][p], lo[p], hi[p]);
        int oc = oc0 + 2*opi;
        if (oc < KK) {
            float bv = bias[k*KK + oc];
            float4 v4;
            v4.x = fmaxf(lo[0] + bv, 0.f);
            v4.y = fmaxf(lo[1] + bv, 0.f);
            v4.z = fmaxf(lo[2] + bv, 0.f);
            v4.w = fmaxf(lo[3] + bv, 0.f);
            *(float4*)(outp + (size_t)oc*HW + oy*W + ox) = v4;
        }
        if (oc + 1 < KK) {
            float bv = bias[k*KK + oc + 1];
            float4 v4;
            v4.x = fmaxf(hi[0] + bv, 0.f);
            v4.y = fmaxf(hi[1] + bv, 0.f);
            v4.z = fmaxf(hi[2] + bv, 0.f);
            v4.w = fmaxf(hi[3] + bv, 0.f);
            *(float4*)(outp + (size_t)(oc+1)*HW + oy*W + ox) = v4;
        }
    }
}

// ---------------------------------------------------------------------------
// Adaptive separable conv (R5-proven version): 1 output px per thread,
// packed f32x2 over taps with parity phase. grid: (W/32, H/8, NB), block (32,8)
// ---------------------------------------------------------------------------
__global__ void __launch_bounds__(256)
sepconv2_kernel(const float* __restrict__ i1, const float* __restrict__ i2,
                const float* __restrict__ gk, float* __restrict__ out)
{
    const int SW = 84;
    int b   = blockIdx.z;
    int gx0 = blockIdx.x * 32;
    int gy0 = blockIdx.y * 8;
    int tx  = threadIdx.x, ty = threadIdx.y;
    int tid = ty * 32 + tx;
    int y = gy0 + ty, x = gx0 + tx;
    int q = tx & 1;
    int col0 = tx - q;

    __shared__ __align__(16) float s_img[58 * SW];

    float acc[3] = {0.f, 0.f, 0.f};

    #pragma unroll 1
    for (int im = 0; im < 2; im++) {
        const float* ip  = im ? i2 : i1;
        const float* kvp = gk + (((size_t)(im*2 + 0)*NB + b)*KK)*HW + (size_t)y*W + x;
        const float* khp = gk + (((size_t)(im*2 + 1)*NB + b)*KK)*HW + (size_t)y*W + x;

        ull KP[26];
        #pragma unroll
        for (int m = 0; m < 26; m++) {
            int t0 = 2*m - q, t1 = 2*m + 1 - q;
            float lo = ((unsigned)t0 < KK) ? khp[(size_t)t0 * HW] : 0.f;
            float hi = ((unsigned)t1 < KK) ? khp[(size_t)t1 * HW] : 0.f;
            KP[m] = pack2(lo, hi);
        }

        #pragma unroll 1
        for (int c = 0; c < 3; c++) {
            const float* cp = ip + ((size_t)b*3 + c) * HP * WPP;
            __syncthreads();
            for (int i = tid; i < 58*SW; i += 256) {
                int rr = i / SW, cc = i % SW;
                s_img[i] = (cc < 82) ? cp[(size_t)(gy0 + rr)*WPP + gx0 + cc] : 0.f;
            }
            __syncthreads();

            ull acc2 = 0ULL;
            #pragma unroll 1
            for (int i = 0; i < KK; i++) {
                const ull* rp = (const ull*)(s_img + (ty + i)*SW + col0);
                ull hs = 0ULL;
                #pragma unroll
                for (int m = 0; m < 26; m++) hs = ffma2(KP[m], rp[m], hs);
                float kv = kvp[(size_t)i * HW];
                acc2 = ffma2(pack2(kv, kv), hs, acc2);
            }
            float lo, hi; unpack2(acc2, lo, hi);
            acc[c] += lo + hi;
        }
    }

    size_t ob = ((size_t)b*3)*HW + (size_t)y*W + x;
    out[ob]        = acc[0];
    out[ob + HW]   = acc[1];
    out[ob + 2*HW] = acc[2];
}

// ---------------------------------------------------------------------------
extern "C" void kernel_launch(void* const* d_in, const int* in_sizes, int n_in,
                              void* d_out, int out_size)
{
    const float* x  = (const float*)d_in[0];
    const float* i1 = (const float*)d_in[1];
    const float* i2 = (const float*)d_in[2];
    const float* W1 = (const float*)d_in[3];
    const float* B1 = (const float*)d_in[4];
    const float* W2 = (const float*)d_in[5];
    const float* B2 = (const float*)d_in[6];
    const float* W3 = (const float*)d_in[7];
    const float* B3 = (const float*)d_in[8];
    float* out = (float*)d_out;

    float* up = nullptr; float* t1 = nullptr; float* t2 = nullptr; float* kk = nullptr;
    float2* wp1 = nullptr; float2* wp2 = nullptr; float2* wp3 = nullptr;
    cudaGetSymbolAddress((void**)&up, g_up);
    cudaGetSymbolAddress((void**)&t1, g_t1);
    cudaGetSymbolAddress((void**)&t2, g_t2);
    cudaGetSymbolAddress((void**)&kk, g_k);
    cudaGetSymbolAddress((void**)&wp1, g_wp1);
    cudaGetSymbolAddress((void**)&wp2, g_wp2);
    cudaGetSymbolAddress((void**)&wp3, g_wp3);

    size_t smem64 = (size_t)(64*180 + 4*18*72) * sizeof(float);
    size_t smem51 = (size_t)(51*180 + 4*18*72) * sizeof(float);
    cudaFuncSetAttribute(conv3x3_relu6<64, false>,
                         cudaFuncAttributeMaxDynamicSharedMemorySize, (int)smem64);
    cudaFuncSetAttribute(conv3x3_relu6<51, true>,
                         cudaFuncAttributeMaxDynamicSharedMemorySize, (int)smem51);

    // 0) pack weights (tiny)
    {
        int t64 = 4*3*64*90, t51 = 4*3*51*90;
        pack_weights<<<(t64 + 255)/256, 256>>>(W1, wp1, 64);
        pack_weights<<<(t51 + 255)/256, 256>>>(W2, wp2, 51);
        pack_weights<<<(t51 + 255)/256, 256>>>(W3, wp3, 51);
    }

    // 1) upsample features
    {
        int n = NB*CF*H*W;
        upsample_kernel<<<(n + 255)/256, 256>>>(x, up);
    }

    // 2) three conv stages
    dim3 cgrid(W/64, H/16, 4*NB*3);
    conv3x3_relu6<64, false><<<cgrid, 256, smem64>>>(up, wp1, B1, t1);
    conv3x3_relu6<51, true ><<<cgrid, 256, smem51>>>(t1, wp2, B2, t2);
    conv3x3_relu6<51, true ><<<cgrid, 256, smem51>>>(t2, wp3, B3, kk);

    // 3) separable filtering of both images + sum
    {
        dim3 g(W/32, H/8, NB);
        dim3 blk(32, 8);
        sepconv2_kernel<<<g, blk>>>(i1, i2, kk, out);
    }
}